// round 11
// baseline (speedup 1.0000x reference)
#include <cuda_runtime.h>

typedef unsigned long long ull;

__device__ __forceinline__ ull pack2(float a, float b) {
    ull r;
    asm("mov.b64 %0, {%1, %2};" : "=l"(r) : "f"(a), "f"(b));
    return r;
}
__device__ __forceinline__ void unpack2(ull v, float& a, float& b) {
    asm("mov.b64 {%0, %1}, %2;" : "=f"(a), "=f"(b) : "l"(v));
}
__device__ __forceinline__ void ffma2(ull& d, ull a, ull b) {
    asm("fma.rn.f32x2 %0, %1, %2, %0;" : "+l"(d) : "l"(a), "l"(b));
}
__device__ __forceinline__ ull fmul2(ull a, ull b) {
    ull r;
    asm("mul.rn.f32x2 %0, %1, %2;" : "=l"(r) : "l"(a), "l"(b));
    return r;
}
__device__ __forceinline__ ull fadd2(ull a, ull b) {
    ull r;
    asm("add.rn.f32x2 %0, %1, %2;" : "=l"(r) : "l"(a), "l"(b));
    return r;
}

// CNOT-ring row permutation for layer with range r: dest row i <- src row q
__device__ __forceinline__ int cnot_perm(int i, int r) {
    int q = i;
#pragma unroll
    for (int m = 3; m >= 0; m--) {
        int tt = (m + r) & 3;
        int cb = 1 << (3 - m), tb = 1 << (3 - tt);
        if (q & cb) q ^= tb;
    }
    return q;
}

// ---------------------------------------------------------------------------
// Fused kernel: overlapped prologue, paired-coefficient LDS.128 mainloop,
// packed (f32x2) norm + epilogue.
// out[b][ch][y][x] = min(8 * |U_ch . p|^2 / ||p||^2, 1)
// ---------------------------------------------------------------------------
__global__ __launch_bounds__(256, 3)
void qconv_kernel(const float* __restrict__ x, const float* __restrict__ w,
                  float* __restrict__ out) {
    __shared__ __align__(16) ulonglong2 sW2[16][5];
    __shared__ float2 gates[8][4];
    __shared__ float2 sL1[16][16];
    __shared__ float2 sL2[16][16];

    const int tid = threadIdx.y * 64 + threadIdx.x;
    const int b  = blockIdx.z;
    const int x0 = threadIdx.x * 4;                       // 0..252
    const int r0 = blockIdx.y * 8 + threadIdx.y * 2;      // 0..254
    const float* xin = x + (size_t)b * 65536;

    // ---- (1) Issue input loads first: 4 rows x 6 cols, pad = 0.01 ----
    float v[4][6];
#pragma unroll
    for (int i = 0; i < 4; i++) {
        int ry = r0 - 1 + i;
        if (ry >= 0 && ry < 256) {
            const float* rp = xin + ry * 256;
            float4 q = *(const float4*)(rp + x0);
            v[i][1] = q.x; v[i][2] = q.y; v[i][3] = q.z; v[i][4] = q.w;
            v[i][0] = (x0 > 0)   ? rp[x0 - 1] : 0.01f;
            v[i][5] = (x0 < 252) ? rp[x0 + 4] : 0.01f;
        } else {
#pragma unroll
            for (int c = 0; c < 6; c++) v[i][c] = 0.01f;
        }
    }

    // ---- (2) Build unitary (overlaps input latency) ----
    {
        const int i = tid >> 4, j = tid & 15;

        if (tid < 32) {
            int g = tid >> 2, e = tid & 3;
            int bi = e >> 1, bj = e & 1;
            float phi = w[g * 3 + 0];
            float th  = w[g * 3 + 1];
            float om  = w[g * 3 + 2];
            float sh, chf;
            __sincosf(0.5f * th, &sh, &chf);
            float mag, phs;
            if (!bi && !bj)      { mag =  chf; phs = -0.5f * (phi + om); }
            else if (!bi &&  bj) { mag = -sh;  phs =  0.5f * (phi - om); }
            else if ( bi && !bj) { mag =  sh;  phs = -0.5f * (phi - om); }
            else                 { mag =  chf; phs =  0.5f * (phi + om); }
            float sp, cp;
            __sincosf(phs, &sp, &cp);
            gates[g][e] = make_float2(mag * cp, mag * sp);
        }
        __syncthreads();

        {
            float2 v1 = make_float2(1.f, 0.f);
            float2 v2 = make_float2(1.f, 0.f);
#pragma unroll
            for (int wi = 0; wi < 4; wi++) {
                int bi = (i >> (3 - wi)) & 1;
                int bj = (j >> (3 - wi)) & 1;
                float2 e1 = gates[wi][bi * 2 + bj];
                float2 e2 = gates[4 + wi][bi * 2 + bj];
                v1 = make_float2(v1.x * e1.x - v1.y * e1.y, v1.x * e1.y + v1.y * e1.x);
                v2 = make_float2(v2.x * e2.x - v2.y * e2.y, v2.x * e2.y + v2.y * e2.x);
            }
            sL1[i][j] = v1;
            sL2[i][j] = v2;
        }
        __syncthreads();

        if (j < 9) {
            const int iq = cnot_perm(i, 2);
            float2 acc = make_float2(0.f, 0.f);
#pragma unroll
            for (int k = 0; k < 16; k++) {
                const int kq = cnot_perm(k, 1);   // compile-time constant
                float2 a = sL2[iq][k];
                float2 bb = sL1[kq][j];
                acc.x += a.x * bb.x - a.y * bb.y;
                acc.y += a.x * bb.y + a.y * bb.x;
            }
            ((ull*)sW2)[i * 10 + j] = pack2(acc.x, acc.y);
        }
    }

    // ---- (3) Packed norm + patch packing (inputs have arrived) ----
    ull pp[4][6];
#pragma unroll
    for (int i = 0; i < 4; i++)
#pragma unroll
        for (int c = 0; c < 6; c++) pp[i][c] = pack2(v[i][c], v[i][c]);

    ull invp[2][2];      // invp[r][q] = (8/s) for pixels (2q, 2q+1) of row r
    {
        // packed pixel-pair squares: pq[i][q] holds (v[2q]^2.., ) per 3-tap window
        // build packed pairs (v[c], v[c+1]) transiently for the separable sums
        ull hp[4][2];
#pragma unroll
        for (int i = 0; i < 4; i++) {
            ull p01 = pack2(v[i][0], v[i][1]);
            ull p12 = pack2(v[i][1], v[i][2]);
            ull p23 = pack2(v[i][2], v[i][3]);
            ull p34 = pack2(v[i][3], v[i][4]);
            ull p45 = pack2(v[i][4], v[i][5]);
            // h[c] = v[c]^2+v[c+1]^2+v[c+2]^2 for c pairs (0,1) and (2,3)
            hp[i][0] = fadd2(fadd2(fmul2(p01, p01), fmul2(p12, p12)), fmul2(p23, p23));
            hp[i][1] = fadd2(fadd2(fmul2(p23, p23), fmul2(p34, p34)), fmul2(p45, p45));
        }
#pragma unroll
        for (int r = 0; r < 2; r++)
#pragma unroll
            for (int q = 0; q < 2; q++) {
                ull s = fadd2(fadd2(hp[r][q], hp[r + 1][q]), hp[r + 2][q]);
                float s0, s1;
                unpack2(s, s0, s1);
                invp[r][q] = pack2(__fdividef(8.0f, fmaxf(s0, 1e-24f)),
                                   __fdividef(8.0f, fmaxf(s1, 1e-24f)));
            }
    }

    __syncthreads();   // sW2 ready

    // ---- (4) Channel mainloop ----
    float* ob = out + (size_t)b * 16 * 65536 + (size_t)r0 * 256 + x0;

#pragma unroll 1
    for (int ch = 0; ch < 16; ch++) {
        ull C[9];
        {
            const ulonglong2* wch = &sW2[ch][0];
            ulonglong2 p0 = wch[0];
            ulonglong2 p1 = wch[1];
            ulonglong2 p2 = wch[2];
            ulonglong2 p3 = wch[3];
            C[0] = p0.x; C[1] = p0.y;
            C[2] = p1.x; C[3] = p1.y;
            C[4] = p2.x; C[5] = p2.y;
            C[6] = p3.x; C[7] = p3.y;
            C[8] = ((const ull*)wch)[8];
        }

        ull acc[2][4];
#pragma unroll
        for (int r = 0; r < 2; r++)
#pragma unroll
            for (int c = 0; c < 4; c++) acc[r][c] = 0ULL;

#pragma unroll
        for (int dr = 0; dr < 3; dr++)
#pragma unroll
            for (int dc = 0; dc < 3; dc++) {
                ull cf = C[dr * 3 + dc];
#pragma unroll
                for (int r = 0; r < 2; r++)
#pragma unroll
                    for (int c = 0; c < 4; c++)
                        ffma2(acc[r][c], cf, pp[r + dr][c + dc]);
            }

        // Packed epilogue: per pixel pair — two self-squares (rt2), two scalar
        // cross-adds, one packed multiply by inv, min on ALU pipe.
#pragma unroll
        for (int r = 0; r < 2; r++) {
            float res[4];
#pragma unroll
            for (int q = 0; q < 2; q++) {
                ull m0 = fmul2(acc[r][2 * q],     acc[r][2 * q]);
                ull m1 = fmul2(acc[r][2 * q + 1], acc[r][2 * q + 1]);
                float a0, b0, a1, b1;
                unpack2(m0, a0, b0);
                unpack2(m1, a1, b1);
                ull sc = fmul2(pack2(a0 + b0, a1 + b1), invp[r][q]);
                float f0, f1;
                unpack2(sc, f0, f1);
                res[2 * q]     = fminf(f0, 1.0f);
                res[2 * q + 1] = fminf(f1, 1.0f);
            }
            *(float4*)(ob + (size_t)r * 256) =
                make_float4(res[0], res[1], res[2], res[3]);
        }
        ob += 65536;
    }
}

extern "C" void kernel_launch(void* const* d_in, const int* in_sizes, int n_in,
                              void* d_out, int out_size) {
    const float* x = (const float*)d_in[0];        // (32,1,256,256) fp32
    const float* w = (const float*)d_in[1];        // (2,4,3) fp32
    float* out = (float*)d_out;                    // (32,16,256,256) fp32

    dim3 block(64, 4, 1);
    dim3 grid(1, 32, 32);
    qconv_kernel<<<grid, block>>>(x, w, out);
}

// round 13
// speedup vs baseline: 1.1211x; 1.1211x over previous
#include <cuda_runtime.h>

typedef unsigned long long ull;

__device__ __forceinline__ ull pack2(float a, float b) {
    ull r;
    asm("mov.b64 %0, {%1, %2};" : "=l"(r) : "f"(a), "f"(b));
    return r;
}
__device__ __forceinline__ void unpack2(ull v, float& a, float& b) {
    asm("mov.b64 {%0, %1}, %2;" : "=f"(a), "=f"(b) : "l"(v));
}
__device__ __forceinline__ void ffma2(ull& d, ull a, ull b) {
    asm("fma.rn.f32x2 %0, %1, %2, %0;" : "+l"(d) : "l"(a), "l"(b));
}

// CNOT-ring row permutation for layer with range r: dest row i <- src row q
__device__ __forceinline__ int cnot_perm(int i, int r) {
    int q = i;
#pragma unroll
    for (int m = 3; m >= 0; m--) {
        int tt = (m + r) & 3;
        int cb = 1 << (3 - m), tb = 1 << (3 - tt);
        if (q & cb) q ^= tb;
    }
    return q;
}

// ---------------------------------------------------------------------------
// Fused kernel: overlapped prologue, paired-coefficient LDS.128 mainloop with
// one-pair cross-channel prefetch, scalar epilogue.
// out[b][ch][y][x] = min(8 * |U_ch . p|^2 / ||p||^2, 1)
// ---------------------------------------------------------------------------
__global__ __launch_bounds__(256, 3)
void qconv_kernel(const float* __restrict__ x, const float* __restrict__ w,
                  float* __restrict__ out) {
    __shared__ __align__(16) ulonglong2 sW2[16][5];
    __shared__ float2 gates[8][4];
    __shared__ float2 sL1[16][16];
    __shared__ float2 sL2[16][16];

    const int tid = threadIdx.y * 64 + threadIdx.x;
    const int b  = blockIdx.z;
    const int x0 = threadIdx.x * 4;                       // 0..252
    const int r0 = blockIdx.y * 8 + threadIdx.y * 2;      // 0..254
    const float* xin = x + (size_t)b * 65536;

    // ---- (1) Issue input loads first: 4 rows x 6 cols, pad = 0.01 ----
    float v[4][6];
#pragma unroll
    for (int i = 0; i < 4; i++) {
        int ry = r0 - 1 + i;
        if (ry >= 0 && ry < 256) {
            const float* rp = xin + ry * 256;
            float4 q = *(const float4*)(rp + x0);
            v[i][1] = q.x; v[i][2] = q.y; v[i][3] = q.z; v[i][4] = q.w;
            v[i][0] = (x0 > 0)   ? rp[x0 - 1] : 0.01f;
            v[i][5] = (x0 < 252) ? rp[x0 + 4] : 0.01f;
        } else {
#pragma unroll
            for (int c = 0; c < 6; c++) v[i][c] = 0.01f;
        }
    }

    // ---- (2) Build unitary (overlaps input latency) ----
    {
        const int i = tid >> 4, j = tid & 15;

        if (tid < 32) {
            int g = tid >> 2, e = tid & 3;
            int bi = e >> 1, bj = e & 1;
            float phi = w[g * 3 + 0];
            float th  = w[g * 3 + 1];
            float om  = w[g * 3 + 2];
            float sh, chf;
            __sincosf(0.5f * th, &sh, &chf);
            float mag, phs;
            if (!bi && !bj)      { mag =  chf; phs = -0.5f * (phi + om); }
            else if (!bi &&  bj) { mag = -sh;  phs =  0.5f * (phi - om); }
            else if ( bi && !bj) { mag =  sh;  phs = -0.5f * (phi - om); }
            else                 { mag =  chf; phs =  0.5f * (phi + om); }
            float sp, cp;
            __sincosf(phs, &sp, &cp);
            gates[g][e] = make_float2(mag * cp, mag * sp);
        }
        __syncthreads();

        {
            float2 v1 = make_float2(1.f, 0.f);
            float2 v2 = make_float2(1.f, 0.f);
#pragma unroll
            for (int wi = 0; wi < 4; wi++) {
                int bi = (i >> (3 - wi)) & 1;
                int bj = (j >> (3 - wi)) & 1;
                float2 e1 = gates[wi][bi * 2 + bj];
                float2 e2 = gates[4 + wi][bi * 2 + bj];
                v1 = make_float2(v1.x * e1.x - v1.y * e1.y, v1.x * e1.y + v1.y * e1.x);
                v2 = make_float2(v2.x * e2.x - v2.y * e2.y, v2.x * e2.y + v2.y * e2.x);
            }
            sL1[i][j] = v1;
            sL2[i][j] = v2;
        }
        __syncthreads();

        if (j < 9) {
            const int iq = cnot_perm(i, 2);
            float2 acc = make_float2(0.f, 0.f);
#pragma unroll
            for (int k = 0; k < 16; k++) {
                const int kq = cnot_perm(k, 1);   // compile-time constant
                float2 a = sL2[iq][k];
                float2 bb = sL1[kq][j];
                acc.x += a.x * bb.x - a.y * bb.y;
                acc.y += a.x * bb.y + a.y * bb.x;
            }
            ((ull*)sW2)[i * 10 + j] = pack2(acc.x, acc.y);
        }
    }

    // ---- (3) Consume inputs (now arrived) before the last barrier ----
    float inv[2][4];
    {
        float h[4][4];
#pragma unroll
        for (int i = 0; i < 4; i++) {
            float sq[6];
#pragma unroll
            for (int c = 0; c < 6; c++) sq[c] = v[i][c] * v[i][c];
#pragma unroll
            for (int c = 0; c < 4; c++) h[i][c] = sq[c] + sq[c + 1] + sq[c + 2];
        }
#pragma unroll
        for (int r = 0; r < 2; r++)
#pragma unroll
            for (int c = 0; c < 4; c++) {
                float s = h[r][c] + h[r + 1][c] + h[r + 2][c];
                inv[r][c] = (s > 1e-24f) ? __fdividef(8.0f, s) : 0.0f;
            }
    }
    ull pp[4][6];
#pragma unroll
    for (int i = 0; i < 4; i++)
#pragma unroll
        for (int c = 0; c < 6; c++) pp[i][c] = pack2(v[i][c], v[i][c]);

    __syncthreads();   // sW2 ready

    // ---- (4) Channel mainloop with one-pair cross-channel prefetch ----
    float* ob = out + (size_t)b * 16 * 65536 + (size_t)r0 * 256 + x0;

    ulonglong2 nextP0 = sW2[0][0];   // taps (0,1) of channel 0

#pragma unroll 1
    for (int ch = 0; ch < 16; ch++) {
        ull C[9];
        C[0] = nextP0.x; C[1] = nextP0.y;
        {
            const ulonglong2* wch = &sW2[ch][0];
            ulonglong2 p1 = wch[1];
            ulonglong2 p2 = wch[2];
            ulonglong2 p3 = wch[3];
            C[2] = p1.x; C[3] = p1.y;
            C[4] = p2.x; C[5] = p2.y;
            C[6] = p3.x; C[7] = p3.y;
            C[8] = ((const ull*)wch)[8];
        }

        ull acc[2][4];
#pragma unroll
        for (int r = 0; r < 2; r++)
#pragma unroll
            for (int c = 0; c < 4; c++) acc[r][c] = 0ULL;

#pragma unroll
        for (int dr = 0; dr < 3; dr++)
#pragma unroll
            for (int dc = 0; dc < 3; dc++) {
                ull cf = C[dr * 3 + dc];
#pragma unroll
                for (int r = 0; r < 2; r++)
#pragma unroll
                    for (int c = 0; c < 4; c++)
                        ffma2(acc[r][c], cf, pp[r + dr][c + dc]);
            }

        // Prefetch next channel's first tap pair before the epilogue/stores,
        // so the next iteration's first FMAs never wait on LDS.
        if (ch < 15) nextP0 = sW2[ch + 1][0];

#pragma unroll
        for (int r = 0; r < 2; r++) {
            float res[4];
#pragma unroll
            for (int c = 0; c < 4; c++) {
                float re, im;
                unpack2(acc[r][c], re, im);
                float mag = re * re + im * im;
                res[c] = fminf(mag * inv[r][c], 1.0f);
            }
            *(float4*)(ob + (size_t)r * 256) =
                make_float4(res[0], res[1], res[2], res[3]);
        }
        ob += 65536;
    }
}

extern "C" void kernel_launch(void* const* d_in, const int* in_sizes, int n_in,
                              void* d_out, int out_size) {
    const float* x = (const float*)d_in[0];        // (32,1,256,256) fp32
    const float* w = (const float*)d_in[1];        // (2,4,3) fp32
    float* out = (float*)d_out;                    // (32,16,256,256) fp32

    dim3 block(64, 4, 1);
    dim3 grid(1, 32, 32);
    qconv_kernel<<<grid, block>>>(x, w, out);
}